// round 6
// baseline (speedup 1.0000x reference)
#include <cuda_runtime.h>
#include <cuda_fp16.h>
#include <cstdint>

// Problem constants
#define N_TOK 8192
#define C_DIM 1024
#define F_DIM 4096
#define E_NUM 8
#define S_SLOTS (N_TOK * 2)
#define CAP 2048

// ---------------- scratch (static device globals) ----------------------------
__device__ __half g_disp[(size_t)E_NUM * CAP * C_DIM];   // 32 MB fp16
__device__ __half g_h[(size_t)E_NUM * CAP * F_DIM];      // 128 MB fp16
__device__ __half g_W1h[(size_t)E_NUM * F_DIM * C_DIM];  // W1^T per expert [F][C] fp16
__device__ __half g_W2h[(size_t)E_NUM * C_DIM * F_DIM];  // W2^T per expert [C][F] fp16
__device__ int    g_eidx[S_SLOTS];
__device__ float  g_wf[S_SLOTS];
__device__ int    g_loc[S_SLOTS];
__device__ int    g_inv[E_NUM * CAP];    // expert-slot -> dispatch slot id
__device__ int    g_cnt[E_NUM];
__device__ float  g_probs_sum[E_NUM];

// ---------------- helpers ----------------------------------------------------
__device__ __forceinline__ float gelu_tanh(float x) {
    const float k0 = 0.7978845608028654f;
    float x3 = x * x * x;
    float t = tanhf(k0 * (x + 0.044715f * x3));
    return 0.5f * x * (1.0f + t);
}

// fp16 m16n8k16, fp32 accumulate
__device__ __forceinline__ void mma_f16(float* d, const uint32_t* a, const uint32_t* b) {
    asm volatile(
        "mma.sync.aligned.m16n8k16.row.col.f32.f16.f16.f32 "
        "{%0,%1,%2,%3}, {%4,%5,%6,%7}, {%8,%9}, {%0,%1,%2,%3};"
        : "+f"(d[0]), "+f"(d[1]), "+f"(d[2]), "+f"(d[3])
        : "r"(a[0]), "r"(a[1]), "r"(a[2]), "r"(a[3]), "r"(b[0]), "r"(b[1]));
}

__device__ __forceinline__ void cp_async16(uint32_t smem_dst, const void* gmem_src) {
    asm volatile("cp.async.cg.shared.global [%0], [%1], 16;\n" :: "r"(smem_dst), "l"(gmem_src));
}
__device__ __forceinline__ void cp_commit() {
    asm volatile("cp.async.commit_group;\n");
}
template <int N>
__device__ __forceinline__ void cp_wait() {
    asm volatile("cp.async.wait_group %0;\n" :: "n"(N));
}

// ---------------- init / zero-out ---------------------------------------------
__global__ void init_kernel() {
    int t = threadIdx.x;
    if (t < E_NUM) g_probs_sum[t] = 0.0f;
}

__global__ void zero_out_kernel(float* __restrict__ out) {
    size_t i = (size_t)blockIdx.x * blockDim.x + threadIdx.x;   // float4 index
    ((float4*)out)[i] = make_float4(0.f, 0.f, 0.f, 0.f);
}

// ---------------- weight transpose + fp16 convert: [E][K][N] -> [E][N][K] -----
// 64x64 tiles, 256 threads: float4 reads, 16B half stores.
__global__ void transpose_h_kernel(const float* __restrict__ src,
                                   __half* __restrict__ dst, int K, int N) {
    __shared__ float t[64][65];
    int e = blockIdx.z;
    const float* s = src + (size_t)e * K * N;
    __half* d = dst + (size_t)e * N * K;
    int n0 = blockIdx.x * 64, k0 = blockIdx.y * 64;
    int tid = threadIdx.x;

    // load 64 rows x 64 floats
    {
        int r = tid >> 4, c4 = tid & 15;
#pragma unroll
        for (int p = 0; p < 4; p++) {
            float4 v = *(const float4*)(s + (size_t)(k0 + r + p * 16) * N + n0 + c4 * 4);
            t[r + p * 16][c4 * 4 + 0] = v.x;
            t[r + p * 16][c4 * 4 + 1] = v.y;
            t[r + p * 16][c4 * 4 + 2] = v.z;
            t[r + p * 16][c4 * 4 + 3] = v.w;
        }
    }
    __syncthreads();

    // store 64 n-rows x 64 halfs (8 halfs = 16B per thread-chunk)
    {
        int n = tid >> 3, c8 = tid & 7;
#pragma unroll
        for (int p = 0; p < 2; p++) {
            int nn = n + p * 32;
            __half2 h[4];
#pragma unroll
            for (int j = 0; j < 4; j++)
                h[j] = __floats2half2_rn(t[c8 * 8 + 2 * j][nn], t[c8 * 8 + 2 * j + 1][nn]);
            *(uint4*)(d + (size_t)(n0 + nn) * K + k0 + c8 * 8) = *(uint4*)h;
        }
    }
}

// ---------------- gating (float4 x loads) --------------------------------------
__global__ void gate_kernel(const float* __restrict__ x,
                            const float* __restrict__ w_gate,
                            const float* __restrict__ b_gate) {
    __shared__ float sprob[E_NUM];
    int tid = threadIdx.x;
    if (tid < E_NUM) sprob[tid] = 0.0f;
    __syncthreads();

    int warp = tid >> 5, lane = tid & 31;
    int n = blockIdx.x * 8 + warp;
    const float4* xr = (const float4*)(x + (size_t)n * C_DIM);

    float acc[E_NUM];
#pragma unroll
    for (int e = 0; e < E_NUM; e++) acc[e] = 0.0f;

    for (int c4 = lane; c4 < C_DIM / 4; c4 += 32) {
        float4 xv = xr[c4];
        const float4* wb = (const float4*)(w_gate + (size_t)c4 * 4 * E_NUM);
#pragma unroll
        for (int j = 0; j < 4; j++) {
            float xs = (&xv.x)[j];
            float4 wa = wb[2 * j], wc = wb[2 * j + 1];
            acc[0] += xs * wa.x; acc[1] += xs * wa.y;
            acc[2] += xs * wa.z; acc[3] += xs * wa.w;
            acc[4] += xs * wc.x; acc[5] += xs * wc.y;
            acc[6] += xs * wc.z; acc[7] += xs * wc.w;
        }
    }
#pragma unroll
    for (int e = 0; e < E_NUM; e++)
#pragma unroll
        for (int o = 16; o > 0; o >>= 1)
            acc[e] += __shfl_down_sync(0xffffffffu, acc[e], o);

    if (lane == 0) {
        float p[E_NUM];
        float mx = -1e30f;
#pragma unroll
        for (int e = 0; e < E_NUM; e++) { p[e] = acc[e] + b_gate[e]; mx = fmaxf(mx, p[e]); }
        float s = 0.0f;
#pragma unroll
        for (int e = 0; e < E_NUM; e++) { p[e] = expf(p[e] - mx); s += p[e]; }
        float inv = 1.0f / s;
#pragma unroll
        for (int e = 0; e < E_NUM; e++) p[e] *= inv;

        int i0 = 0;
#pragma unroll
        for (int e = 1; e < E_NUM; e++) if (p[e] > p[i0]) i0 = e;
        int i1 = (i0 == 0) ? 1 : 0;
#pragma unroll
        for (int e = 0; e < E_NUM; e++) if (e != i0 && p[e] > p[i1]) i1 = e;

        float w0 = p[i0], w1 = p[i1];
        float ws = w0 + w1 + 1e-9f;
        g_eidx[2 * n]     = i0;
        g_eidx[2 * n + 1] = i1;
        g_wf[2 * n]       = w0 / ws;
        g_wf[2 * n + 1]   = w1 / ws;
#pragma unroll
        for (int e = 0; e < E_NUM; e++) atomicAdd(&sprob[e], p[e]);
    }
    __syncthreads();
    if (tid < E_NUM) atomicAdd(&g_probs_sum[tid], sprob[tid]);
}

// ---------------- FCFS capacity scan + inverse map + aux loss ------------------
__global__ void scan_kernel(float* __restrict__ d_out, int out_size) {
    const int PER = 64;
    int t = threadIdx.x;
    int base = t * PER;

    int cnt[E_NUM];
#pragma unroll
    for (int e = 0; e < E_NUM; e++) cnt[e] = 0;
    for (int i = 0; i < PER; i++) cnt[g_eidx[base + i]]++;

    unsigned long long lo = 0, hi = 0;
#pragma unroll
    for (int e = 0; e < 4; e++) {
        lo |= (unsigned long long)cnt[e] << (16 * e);
        hi |= (unsigned long long)cnt[e + 4] << (16 * e);
    }

    __shared__ unsigned long long s0[256], s1[256];
    s0[t] = lo; s1[t] = hi;
    __syncthreads();
    for (int off = 1; off < 256; off <<= 1) {
        unsigned long long v0 = 0, v1 = 0;
        if (t >= off) { v0 = s0[t - off]; v1 = s1[t - off]; }
        __syncthreads();
        s0[t] += v0; s1[t] += v1;
        __syncthreads();
    }
    unsigned long long p0 = (t > 0) ? s0[t - 1] : 0ULL;
    unsigned long long p1 = (t > 0) ? s1[t - 1] : 0ULL;

    int exc[E_NUM];
#pragma unroll
    for (int e = 0; e < 4; e++) {
        exc[e]     = (int)((p0 >> (16 * e)) & 0xffffULL);
        exc[e + 4] = (int)((p1 >> (16 * e)) & 0xffffULL);
    }
    for (int i = 0; i < PER; i++) {
        int s = base + i;
        int e = g_eidx[s];
        int pos = exc[e]++;
        if (pos < CAP) {
            g_loc[s] = e * CAP + pos;
            g_inv[e * CAP + pos] = s;
        } else {
            g_loc[s] = -1;
        }
    }

    if (t == 0) {
        unsigned long long t0 = s0[255], t1 = s1[255];
        float sumload = 0.0f, load[E_NUM];
#pragma unroll
        for (int e = 0; e < 4; e++) {
            int c0 = (int)((t0 >> (16 * e)) & 0xffffULL);
            int c1 = (int)((t1 >> (16 * e)) & 0xffffULL);
            g_cnt[e]     = min(c0, CAP);
            g_cnt[e + 4] = min(c1, CAP);
            load[e]     = (float)min(c0, CAP);
            load[e + 4] = (float)min(c1, CAP);
        }
#pragma unroll
        for (int e = 0; e < E_NUM; e++) sumload += load[e];
        float fe[E_NUM], sfe = 0.0f;
#pragma unroll
        for (int e = 0; e < E_NUM; e++) { fe[e] = g_probs_sum[e] / (float)N_TOK; sfe += fe[e]; }
        float aux = 0.0f;
#pragma unroll
        for (int e = 0; e < E_NUM; e++) {
            float fn = fe[e] / (sfe + 1e-9f);
            float fa = load[e] / (sumload + 1e-9f);
            float d = fn - fa;
            aux += d * d;
        }
        aux = 0.01f * aux / (float)E_NUM;
        if (out_size > N_TOK * C_DIM)
            d_out[(size_t)N_TOK * C_DIM] = aux;
    }
}

// ---------------- dispatch gather (fp16 convert at write) ----------------------
__global__ void dispatch_kernel(const float* __restrict__ x) {
    int s = blockIdx.x;
    int loc = g_loc[s];
    if (loc < 0) return;
    const float4* src = (const float4*)(x + ((size_t)(s >> 1)) * C_DIM);
    __half* dst = g_disp + (size_t)loc * C_DIM;
    int t = threadIdx.x;  // 128
    float4 v0 = src[2 * t];
    float4 v1 = src[2 * t + 1];
    __half2 h[4];
    h[0] = __floats2half2_rn(v0.x, v0.y);
    h[1] = __floats2half2_rn(v0.z, v0.w);
    h[2] = __floats2half2_rn(v1.x, v1.y);
    h[3] = __floats2half2_rn(v1.z, v1.w);
    *(uint4*)(dst + 8 * t) = *(uint4*)h;
}

// ---------------- grouped GEMM: fp16 mma.sync m16n8k16, 4-stage cp.async ------
#define GBM 128
#define GBN 128
#define GBK 32
#define GST 4
#define LDH 40
#define ASZH (GBM * LDH)
#define BSZH (GBN * LDH)
#define STG_BYTES ((ASZH + BSZH) * 2)
#define GEMM_SMEM_BYTES (GST * STG_BYTES)

// SCATTER=false: Out = half g_h tile (with gelu). SCATTER=true: weighted
// atomic scatter-add of float rows into the token-major output.
template <bool GELU, bool SCATTER, typename OT>
__global__ __launch_bounds__(256, 2)
void gemm_kernel(const __half* __restrict__ A, const __half* __restrict__ Bt,
                 const float* __restrict__ bias, OT* __restrict__ Out,
                 int M, int N, int Kd) {
    int e = blockIdx.z;
    int bm = blockIdx.y, bn = blockIdx.x;
    int cnt = g_cnt[e];
    if (bm * GBM >= cnt) return;

    extern __shared__ __half smem[];
    __half* Asm = smem;
    __half* Bsm = smem + GST * ASZH;

    const __half* Ae = A + (size_t)e * M * Kd;
    const __half* Be = Bt + (size_t)e * N * Kd;

    int tid = threadIdx.x;
    int warp = tid >> 5, lane = tid & 31;
    int g = lane >> 2, tig = lane & 3;
    int wm = warp >> 2;
    int wn = warp & 3;

    uint32_t sA = (uint32_t)__cvta_generic_to_shared(Asm);
    uint32_t sB = (uint32_t)__cvta_generic_to_shared(Bsm);

    const int nK = Kd / GBK;

    auto issue = [&](int kt, int st) {
        uint32_t aBase = sA + (uint32_t)(st * ASZH) * 2;
        uint32_t bBase = sB + (uint32_t)(st * BSZH) * 2;
#pragma unroll
        for (int i = 0; i < 2; i++) {
            int ch = tid + 256 * i;
            int r = ch >> 2, c = (ch & 3) * 8;
            cp_async16(aBase + (uint32_t)(r * LDH + c) * 2,
                       Ae + (size_t)(bm * GBM + r) * Kd + kt * GBK + c);
        }
#pragma unroll
        for (int i = 0; i < 2; i++) {
            int ch = tid + 256 * i;
            int r = ch >> 2, c = (ch & 3) * 8;
            cp_async16(bBase + (uint32_t)(r * LDH + c) * 2,
                       Be + (size_t)(bn * GBN + r) * Kd + kt * GBK + c);
        }
        cp_commit();
    };

#pragma unroll
    for (int s = 0; s < GST - 1; s++) issue(s, s);

    float acc[4][4][4];
#pragma unroll
    for (int i = 0; i < 4; i++)
#pragma unroll
        for (int j = 0; j < 4; j++)
#pragma unroll
            for (int k = 0; k < 4; k++) acc[i][j][k] = 0.0f;

    for (int kt = 0; kt < nK; kt++) {
        int rem = nK - 1 - kt;
        if (rem >= GST - 2) cp_wait<GST - 2>();
        else if (rem == 1)  cp_wait<1>();
        else                cp_wait<0>();
        __syncthreads();

        int nt = kt + GST - 1;
        if (nt < nK) issue(nt, nt % GST);

        const __half* as = Asm + (kt % GST) * ASZH;
        const __half* bs = Bsm + (kt % GST) * BSZH;

#pragma unroll
        for (int kk = 0; kk < 2; kk++) {
            int kb = kk * 16;
            uint32_t af[4][4];
#pragma unroll
            for (int mt = 0; mt < 4; mt++) {
                int r0 = wm * 64 + mt * 16 + g;
                af[mt][0] = *(const uint32_t*)&as[r0 * LDH + kb + 2 * tig];
                af[mt][1] = *(const uint32_t*)&as[(r0 + 8) * LDH + kb + 2 * tig];
                af[mt][2] = *(const uint32_t*)&as[r0 * LDH + kb + 8 + 2 * tig];
                af[mt][3] = *(const uint32_t*)&as[(r0 + 8) * LDH + kb + 8 + 2 * tig];
            }
            uint32_t bf[4][2];
#pragma unroll
            for (int nt2 = 0; nt2 < 4; nt2++) {
                int c0 = wn * 32 + nt2 * 8 + g;
                bf[nt2][0] = *(const uint32_t*)&bs[c0 * LDH + kb + 2 * tig];
                bf[nt2][1] = *(const uint32_t*)&bs[c0 * LDH + kb + 8 + 2 * tig];
            }
#pragma unroll
            for (int mt = 0; mt < 4; mt++)
#pragma unroll
                for (int nt2 = 0; nt2 < 4; nt2++)
                    mma_f16(acc[mt][nt2], af[mt], bf[nt2]);
        }
        __syncthreads();
    }

    // epilogue
#pragma unroll
    for (int mt = 0; mt < 4; mt++) {
        int lr0 = wm * 64 + mt * 16 + g;
        int gr0 = bm * GBM + lr0;
        int gr1 = gr0 + 8;

        int tok0 = 0, tok1 = 0;
        float sw0 = 0.0f, sw1 = 0.0f;
        bool k0 = true, k1 = true;
        if (SCATTER) {
            k0 = gr0 < cnt; k1 = gr1 < cnt;
            if (k0) { int sl = g_inv[e * CAP + gr0]; tok0 = sl >> 1; sw0 = g_wf[sl]; }
            if (k1) { int sl = g_inv[e * CAP + gr1]; tok1 = sl >> 1; sw1 = g_wf[sl]; }
        }

#pragma unroll
        for (int nt2 = 0; nt2 < 4; nt2++) {
            int c0 = bn * GBN + wn * 32 + nt2 * 8 + 2 * tig;
            float bv0 = bias[(size_t)e * N + c0];
            float bv1 = bias[(size_t)e * N + c0 + 1];
            float v00 = acc[mt][nt2][0] + bv0;
            float v01 = acc[mt][nt2][1] + bv1;
            float v10 = acc[mt][nt2][2] + bv0;
            float v11 = acc[mt][nt2][3] + bv1;
            if (GELU) {
                v00 = gelu_tanh(v00); v01 = gelu_tanh(v01);
                v10 = gelu_tanh(v10); v11 = gelu_tanh(v11);
            }
            if (SCATTER) {
                float* fo = (float*)Out;
                if (k0) {
                    atomicAdd(fo + (size_t)tok0 * N + c0,     sw0 * v00);
                    atomicAdd(fo + (size_t)tok0 * N + c0 + 1, sw0 * v01);
                }
                if (k1) {
                    atomicAdd(fo + (size_t)tok1 * N + c0,     sw1 * v10);
                    atomicAdd(fo + (size_t)tok1 * N + c0 + 1, sw1 * v11);
                }
            } else {
                __half* ho = (__half*)Out + (size_t)e * M * N;
                *(__half2*)(ho + (size_t)gr0 * N + c0) = __floats2half2_rn(v00, v01);
                *(__half2*)(ho + (size_t)gr1 * N + c0) = __floats2half2_rn(v10, v11);
            }
        }
    }
}

// ---------------- launcher ----------------------------------------------------
extern "C" void kernel_launch(void* const* d_in, const int* in_sizes, int n_in,
                              void* d_out, int out_size) {
    const float* x      = (const float*)d_in[0];
    const float* w_gate = (const float*)d_in[1];
    const float* b_gate = (const float*)d_in[2];
    const float* W1     = (const float*)d_in[3];
    const float* b1     = (const float*)d_in[4];
    const float* W2     = (const float*)d_in[5];
    const float* b2     = (const float*)d_in[6];
    float* out = (float*)d_out;

    cudaFuncSetAttribute((const void*)gemm_kernel<true, false, __half>,
                         cudaFuncAttributeMaxDynamicSharedMemorySize, GEMM_SMEM_BYTES);
    cudaFuncSetAttribute((const void*)gemm_kernel<false, true, float>,
                         cudaFuncAttributeMaxDynamicSharedMemorySize, GEMM_SMEM_BYTES);

    __half *disp = nullptr, *h = nullptr, *w1h = nullptr, *w2h = nullptr;
    cudaGetSymbolAddress((void**)&disp, g_disp);
    cudaGetSymbolAddress((void**)&h, g_h);
    cudaGetSymbolAddress((void**)&w1h, g_W1h);
    cudaGetSymbolAddress((void**)&w2h, g_W2h);

    init_kernel<<<1, 32>>>();
    zero_out_kernel<<<(N_TOK * C_DIM / 4) / 256, 256>>>(out);

    {
        dim3 blk(256);
        dim3 t1(F_DIM / 64, C_DIM / 64, E_NUM);
        transpose_h_kernel<<<t1, blk>>>(W1, w1h, C_DIM, F_DIM);
        dim3 t2(C_DIM / 64, F_DIM / 64, E_NUM);
        transpose_h_kernel<<<t2, blk>>>(W2, w2h, F_DIM, C_DIM);
    }

    gate_kernel<<<N_TOK / 8, 256>>>(x, w_gate, b_gate);
    scan_kernel<<<1, 256>>>(out, out_size);
    dispatch_kernel<<<S_SLOTS, 128>>>(x);

    {
        dim3 grid1(F_DIM / GBN, CAP / GBM, E_NUM);
        gemm_kernel<true, false, __half><<<grid1, 256, GEMM_SMEM_BYTES>>>(
            disp, w1h, b1, h, CAP, F_DIM, C_DIM);

        dim3 grid2(C_DIM / GBN, CAP / GBM, E_NUM);
        gemm_kernel<false, true, float><<<grid2, 256, GEMM_SMEM_BYTES>>>(
            h, w2h, b2, out, CAP, C_DIM, F_DIM);
    }
}

// round 7
// speedup vs baseline: 1.0140x; 1.0140x over previous
#include <cuda_runtime.h>
#include <cuda_fp16.h>
#include <cstdint>

// Problem constants
#define N_TOK 8192
#define C_DIM 1024
#define F_DIM 4096
#define E_NUM 8
#define S_SLOTS (N_TOK * 2)
#define CAP 2048

// ---------------- scratch (static device globals) ----------------------------
__device__ __half g_disp[(size_t)E_NUM * CAP * C_DIM];   // 32 MB fp16
__device__ __half g_h[(size_t)E_NUM * CAP * F_DIM];      // 128 MB fp16
__device__ float  g_y[(size_t)E_NUM * CAP * C_DIM];      // 64 MB
__device__ __half g_W1h[(size_t)E_NUM * F_DIM * C_DIM];  // W1^T per expert [F][C] fp16
__device__ __half g_W2h[(size_t)E_NUM * C_DIM * F_DIM];  // W2^T per expert [C][F] fp16
__device__ int    g_eidx[S_SLOTS];
__device__ float  g_wf[S_SLOTS];
__device__ int    g_loc[S_SLOTS];
__device__ int    g_cnt[E_NUM];
__device__ float  g_probs_sum[E_NUM];

// ---------------- helpers ----------------------------------------------------
__device__ __forceinline__ float gelu_tanh(float x) {
    const float k0 = 0.7978845608028654f;
    float x3 = x * x * x;
    float t = tanhf(k0 * (x + 0.044715f * x3));
    return 0.5f * x * (1.0f + t);
}

// fp16 m16n8k16, fp32 accumulate
__device__ __forceinline__ void mma_f16(float* d, const uint32_t* a, const uint32_t* b) {
    asm volatile(
        "mma.sync.aligned.m16n8k16.row.col.f32.f16.f16.f32 "
        "{%0,%1,%2,%3}, {%4,%5,%6,%7}, {%8,%9}, {%0,%1,%2,%3};"
        : "+f"(d[0]), "+f"(d[1]), "+f"(d[2]), "+f"(d[3])
        : "r"(a[0]), "r"(a[1]), "r"(a[2]), "r"(a[3]), "r"(b[0]), "r"(b[1]));
}

__device__ __forceinline__ void cp_async16(uint32_t smem_dst, const void* gmem_src) {
    asm volatile("cp.async.cg.shared.global [%0], [%1], 16;\n" :: "r"(smem_dst), "l"(gmem_src));
}
__device__ __forceinline__ void cp_commit() {
    asm volatile("cp.async.commit_group;\n");
}
template <int N>
__device__ __forceinline__ void cp_wait() {
    asm volatile("cp.async.wait_group %0;\n" :: "n"(N));
}

// ---------------- init -------------------------------------------------------
__global__ void init_kernel() {
    int t = threadIdx.x;
    if (t < E_NUM) g_probs_sum[t] = 0.0f;
}

// ---------------- weight transpose + fp16 convert: [E][K][N] -> [E][N][K] -----
// 64x64 tiles, 256 threads: float4 reads, 16B half stores.
__global__ void transpose_h_kernel(const float* __restrict__ src,
                                   __half* __restrict__ dst, int K, int N) {
    __shared__ float t[64][65];
    int e = blockIdx.z;
    const float* s = src + (size_t)e * K * N;
    __half* d = dst + (size_t)e * N * K;
    int n0 = blockIdx.x * 64, k0 = blockIdx.y * 64;
    int tid = threadIdx.x;

    {
        int r = tid >> 4, c4 = tid & 15;
#pragma unroll
        for (int p = 0; p < 4; p++) {
            float4 v = *(const float4*)(s + (size_t)(k0 + r + p * 16) * N + n0 + c4 * 4);
            t[r + p * 16][c4 * 4 + 0] = v.x;
            t[r + p * 16][c4 * 4 + 1] = v.y;
            t[r + p * 16][c4 * 4 + 2] = v.z;
            t[r + p * 16][c4 * 4 + 3] = v.w;
        }
    }
    __syncthreads();

    {
        int n = tid >> 3, c8 = tid & 7;
#pragma unroll
        for (int p = 0; p < 2; p++) {
            int nn = n + p * 32;
            __half2 h[4];
#pragma unroll
            for (int j = 0; j < 4; j++)
                h[j] = __floats2half2_rn(t[c8 * 8 + 2 * j][nn], t[c8 * 8 + 2 * j + 1][nn]);
            *(uint4*)(d + (size_t)(n0 + nn) * K + k0 + c8 * 8) = *(uint4*)h;
        }
    }
}

// ---------------- gating (float4 x loads) --------------------------------------
__global__ void gate_kernel(const float* __restrict__ x,
                            const float* __restrict__ w_gate,
                            const float* __restrict__ b_gate) {
    __shared__ float sprob[E_NUM];
    int tid = threadIdx.x;
    if (tid < E_NUM) sprob[tid] = 0.0f;
    __syncthreads();

    int warp = tid >> 5, lane = tid & 31;
    int n = blockIdx.x * 8 + warp;
    const float4* xr = (const float4*)(x + (size_t)n * C_DIM);

    float acc[E_NUM];
#pragma unroll
    for (int e = 0; e < E_NUM; e++) acc[e] = 0.0f;

    for (int c4 = lane; c4 < C_DIM / 4; c4 += 32) {
        float4 xv = xr[c4];
        const float4* wb = (const float4*)(w_gate + (size_t)c4 * 4 * E_NUM);
#pragma unroll
        for (int j = 0; j < 4; j++) {
            float xs = (&xv.x)[j];
            float4 wa = wb[2 * j], wc = wb[2 * j + 1];
            acc[0] += xs * wa.x; acc[1] += xs * wa.y;
            acc[2] += xs * wa.z; acc[3] += xs * wa.w;
            acc[4] += xs * wc.x; acc[5] += xs * wc.y;
            acc[6] += xs * wc.z; acc[7] += xs * wc.w;
        }
    }
#pragma unroll
    for (int e = 0; e < E_NUM; e++)
#pragma unroll
        for (int o = 16; o > 0; o >>= 1)
            acc[e] += __shfl_down_sync(0xffffffffu, acc[e], o);

    if (lane == 0) {
        float p[E_NUM];
        float mx = -1e30f;
#pragma unroll
        for (int e = 0; e < E_NUM; e++) { p[e] = acc[e] + b_gate[e]; mx = fmaxf(mx, p[e]); }
        float s = 0.0f;
#pragma unroll
        for (int e = 0; e < E_NUM; e++) { p[e] = expf(p[e] - mx); s += p[e]; }
        float inv = 1.0f / s;
#pragma unroll
        for (int e = 0; e < E_NUM; e++) p[e] *= inv;

        int i0 = 0;
#pragma unroll
        for (int e = 1; e < E_NUM; e++) if (p[e] > p[i0]) i0 = e;
        int i1 = (i0 == 0) ? 1 : 0;
#pragma unroll
        for (int e = 0; e < E_NUM; e++) if (e != i0 && p[e] > p[i1]) i1 = e;

        float w0 = p[i0], w1 = p[i1];
        float ws = w0 + w1 + 1e-9f;
        g_eidx[2 * n]     = i0;
        g_eidx[2 * n + 1] = i1;
        g_wf[2 * n]       = w0 / ws;
        g_wf[2 * n + 1]   = w1 / ws;
#pragma unroll
        for (int e = 0; e < E_NUM; e++) atomicAdd(&sprob[e], p[e]);
    }
    __syncthreads();
    if (tid < E_NUM) atomicAdd(&g_probs_sum[tid], sprob[tid]);
}

// ---------------- FCFS capacity scan + aux loss --------------------------------
__global__ void scan_kernel(float* __restrict__ d_out, int out_size) {
    const int PER = 64;
    int t = threadIdx.x;
    int base = t * PER;

    int cnt[E_NUM];
#pragma unroll
    for (int e = 0; e < E_NUM; e++) cnt[e] = 0;
    for (int i = 0; i < PER; i++) cnt[g_eidx[base + i]]++;

    unsigned long long lo = 0, hi = 0;
#pragma unroll
    for (int e = 0; e < 4; e++) {
        lo |= (unsigned long long)cnt[e] << (16 * e);
        hi |= (unsigned long long)cnt[e + 4] << (16 * e);
    }

    __shared__ unsigned long long s0[256], s1[256];
    s0[t] = lo; s1[t] = hi;
    __syncthreads();
    for (int off = 1; off < 256; off <<= 1) {
        unsigned long long v0 = 0, v1 = 0;
        if (t >= off) { v0 = s0[t - off]; v1 = s1[t - off]; }
        __syncthreads();
        s0[t] += v0; s1[t] += v1;
        __syncthreads();
    }
    unsigned long long p0 = (t > 0) ? s0[t - 1] : 0ULL;
    unsigned long long p1 = (t > 0) ? s1[t - 1] : 0ULL;

    int exc[E_NUM];
#pragma unroll
    for (int e = 0; e < 4; e++) {
        exc[e]     = (int)((p0 >> (16 * e)) & 0xffffULL);
        exc[e + 4] = (int)((p1 >> (16 * e)) & 0xffffULL);
    }
    for (int i = 0; i < PER; i++) {
        int s = base + i;
        int e = g_eidx[s];
        int pos = exc[e]++;
        g_loc[s] = (pos < CAP) ? (e * CAP + pos) : -1;
    }

    if (t == 0) {
        unsigned long long t0 = s0[255], t1 = s1[255];
        float sumload = 0.0f, load[E_NUM];
#pragma unroll
        for (int e = 0; e < 4; e++) {
            int c0 = (int)((t0 >> (16 * e)) & 0xffffULL);
            int c1 = (int)((t1 >> (16 * e)) & 0xffffULL);
            g_cnt[e]     = min(c0, CAP);
            g_cnt[e + 4] = min(c1, CAP);
            load[e]     = (float)min(c0, CAP);
            load[e + 4] = (float)min(c1, CAP);
        }
#pragma unroll
        for (int e = 0; e < E_NUM; e++) sumload += load[e];
        float fe[E_NUM], sfe = 0.0f;
#pragma unroll
        for (int e = 0; e < E_NUM; e++) { fe[e] = g_probs_sum[e] / (float)N_TOK; sfe += fe[e]; }
        float aux = 0.0f;
#pragma unroll
        for (int e = 0; e < E_NUM; e++) {
            float fn = fe[e] / (sfe + 1e-9f);
            float fa = load[e] / (sumload + 1e-9f);
            float d = fn - fa;
            aux += d * d;
        }
        aux = 0.01f * aux / (float)E_NUM;
        if (out_size > N_TOK * C_DIM)
            d_out[(size_t)N_TOK * C_DIM] = aux;
    }
}

// ---------------- dispatch gather (fp16 convert at write) ----------------------
__global__ void dispatch_kernel(const float* __restrict__ x) {
    int s = blockIdx.x;
    int loc = g_loc[s];
    if (loc < 0) return;
    const float4* src = (const float4*)(x + ((size_t)(s >> 1)) * C_DIM);
    __half* dst = g_disp + (size_t)loc * C_DIM;
    int t = threadIdx.x;  // 128
    float4 v0 = src[2 * t];
    float4 v1 = src[2 * t + 1];
    __half2 h[4];
    h[0] = __floats2half2_rn(v0.x, v0.y);
    h[1] = __floats2half2_rn(v0.z, v0.w);
    h[2] = __floats2half2_rn(v1.x, v1.y);
    h[3] = __floats2half2_rn(v1.z, v1.w);
    *(uint4*)(dst + 8 * t) = *(uint4*)h;
}

// ---------------- grouped GEMM: fp16 mma.sync m16n8k16, 5-stage cp.async ------
#define GBM 128
#define GBN 128
#define GBK 32
#define GST 5
#define LDH 40
#define ASZH (GBM * LDH)
#define BSZH (GBN * LDH)
#define STG_BYTES ((ASZH + BSZH) * 2)              // 20480
#define GEMM_SMEM_BYTES (GST * STG_BYTES)          // 102400

template <bool GELU, typename OT>
__global__ __launch_bounds__(256, 2)
void gemm_kernel(const __half* __restrict__ A, const __half* __restrict__ Bt,
                 const float* __restrict__ bias, OT* __restrict__ Out,
                 int M, int N, int Kd) {
    int e = blockIdx.z;
    int bm = blockIdx.y, bn = blockIdx.x;
    if (bm * GBM >= g_cnt[e]) return;   // rows never read downstream

    extern __shared__ __half smem[];
    __half* Asm = smem;
    __half* Bsm = smem + GST * ASZH;

    const __half* Ae = A + (size_t)e * M * Kd;
    const __half* Be = Bt + (size_t)e * N * Kd;
    OT* Oe = Out + (size_t)e * M * N;

    int tid = threadIdx.x;
    int warp = tid >> 5, lane = tid & 31;
    int g = lane >> 2, tig = lane & 3;
    int wm = warp >> 2;
    int wn = warp & 3;

    uint32_t sA = (uint32_t)__cvta_generic_to_shared(Asm);
    uint32_t sB = (uint32_t)__cvta_generic_to_shared(Bsm);

    const int nK = Kd / GBK;

    auto issue = [&](int kt, int st) {
        uint32_t aBase = sA + (uint32_t)(st * ASZH) * 2;
        uint32_t bBase = sB + (uint32_t)(st * BSZH) * 2;
#pragma unroll
        for (int i = 0; i < 2; i++) {
            int ch = tid + 256 * i;
            int r = ch >> 2, c = (ch & 3) * 8;
            cp_async16(aBase + (uint32_t)(r * LDH + c) * 2,
                       Ae + (size_t)(bm * GBM + r) * Kd + kt * GBK + c);
        }
#pragma unroll
        for (int i = 0; i < 2; i++) {
            int ch = tid + 256 * i;
            int r = ch >> 2, c = (ch & 3) * 8;
            cp_async16(bBase + (uint32_t)(r * LDH + c) * 2,
                       Be + (size_t)(bn * GBN + r) * Kd + kt * GBK + c);
        }
        cp_commit();
    };

    // prologue: fill stages 0..GST-2
#pragma unroll
    for (int s = 0; s < GST - 1; s++) issue(s, s);

    float acc[4][4][4];
#pragma unroll
    for (int i = 0; i < 4; i++)
#pragma unroll
        for (int j = 0; j < 4; j++)
#pragma unroll
            for (int k = 0; k < 4; k++) acc[i][j][k] = 0.0f;

    for (int kt = 0; kt < nK; kt++) {
        int rem = nK - 1 - kt;   // groups allowed to stay pending
        if (rem >= GST - 2)      cp_wait<GST - 2>();
        else if (rem == 2)       cp_wait<2>();
        else if (rem == 1)       cp_wait<1>();
        else                     cp_wait<0>();
        // Single barrier per iteration: also orders "all warps done reading
        // stage (kt-1)%GST during iter kt-1" before the issue below overwrites it.
        __syncthreads();

        int nt = kt + GST - 1;
        if (nt < nK) issue(nt, nt % GST);

        const __half* as = Asm + (kt % GST) * ASZH;
        const __half* bs = Bsm + (kt % GST) * BSZH;

#pragma unroll
        for (int kk = 0; kk < 2; kk++) {
            int kb = kk * 16;
            uint32_t af[4][4];
#pragma unroll
            for (int mt = 0; mt < 4; mt++) {
                int r0 = wm * 64 + mt * 16 + g;
                af[mt][0] = *(const uint32_t*)&as[r0 * LDH + kb + 2 * tig];
                af[mt][1] = *(const uint32_t*)&as[(r0 + 8) * LDH + kb + 2 * tig];
                af[mt][2] = *(const uint32_t*)&as[r0 * LDH + kb + 8 + 2 * tig];
                af[mt][3] = *(const uint32_t*)&as[(r0 + 8) * LDH + kb + 8 + 2 * tig];
            }
            uint32_t bf[4][2];
#pragma unroll
            for (int nt2 = 0; nt2 < 4; nt2++) {
                int c0 = wn * 32 + nt2 * 8 + g;
                bf[nt2][0] = *(const uint32_t*)&bs[c0 * LDH + kb + 2 * tig];
                bf[nt2][1] = *(const uint32_t*)&bs[c0 * LDH + kb + 8 + 2 * tig];
            }
#pragma unroll
            for (int mt = 0; mt < 4; mt++)
#pragma unroll
                for (int nt2 = 0; nt2 < 4; nt2++)
                    mma_f16(acc[mt][nt2], af[mt], bf[nt2]);
        }
    }

    // epilogue
#pragma unroll
    for (int mt = 0; mt < 4; mt++) {
        int r0 = bm * GBM + wm * 64 + mt * 16 + g;
#pragma unroll
        for (int nt2 = 0; nt2 < 4; nt2++) {
            int c0 = bn * GBN + wn * 32 + nt2 * 8 + 2 * tig;
            float bv0 = bias[(size_t)e * N + c0];
            float bv1 = bias[(size_t)e * N + c0 + 1];
            float v00 = acc[mt][nt2][0] + bv0;
            float v01 = acc[mt][nt2][1] + bv1;
            float v10 = acc[mt][nt2][2] + bv0;
            float v11 = acc[mt][nt2][3] + bv1;
            if (GELU) {
                v00 = gelu_tanh(v00); v01 = gelu_tanh(v01);
                v10 = gelu_tanh(v10); v11 = gelu_tanh(v11);
            }
            if constexpr (sizeof(OT) == 2) {
                *(__half2*)((__half*)Oe + (size_t)r0 * N + c0) = __floats2half2_rn(v00, v01);
                *(__half2*)((__half*)Oe + (size_t)(r0 + 8) * N + c0) = __floats2half2_rn(v10, v11);
            } else {
                *(float2*)((float*)Oe + (size_t)r0 * N + c0) = make_float2(v00, v01);
                *(float2*)((float*)Oe + (size_t)(r0 + 8) * N + c0) = make_float2(v10, v11);
            }
        }
    }
}

// ---------------- combine gather ---------------------------------------------
__global__ void combine_kernel(float* __restrict__ out) {
    int n = blockIdx.x;
    int l0 = g_loc[2 * n], l1 = g_loc[2 * n + 1];
    float w0 = (l0 >= 0) ? g_wf[2 * n] : 0.0f;
    float w1 = (l1 >= 0) ? g_wf[2 * n + 1] : 0.0f;
    const float4* y0 = (const float4*)(g_y + (size_t)max(l0, 0) * C_DIM);
    const float4* y1 = (const float4*)(g_y + (size_t)max(l1, 0) * C_DIM);
    float4* dst = (float4*)(out + (size_t)n * C_DIM);
    int t = threadIdx.x;  // 128
#pragma unroll
    for (int j = 0; j < 2; j++) {
        int idx = t + j * 128;
        float4 a = (l0 >= 0) ? y0[idx] : make_float4(0, 0, 0, 0);
        float4 b = (l1 >= 0) ? y1[idx] : make_float4(0, 0, 0, 0);
        float4 r;
        r.x = w0 * a.x + w1 * b.x;
        r.y = w0 * a.y + w1 * b.y;
        r.z = w0 * a.z + w1 * b.z;
        r.w = w0 * a.w + w1 * b.w;
        dst[idx] = r;
    }
}

// ---------------- launcher ----------------------------------------------------
extern "C" void kernel_launch(void* const* d_in, const int* in_sizes, int n_in,
                              void* d_out, int out_size) {
    const float* x      = (const float*)d_in[0];
    const float* w_gate = (const float*)d_in[1];
    const float* b_gate = (const float*)d_in[2];
    const float* W1     = (const float*)d_in[3];
    const float* b1     = (const float*)d_in[4];
    const float* W2     = (const float*)d_in[5];
    const float* b2     = (const float*)d_in[6];
    float* out = (float*)d_out;

    cudaFuncSetAttribute((const void*)gemm_kernel<true, __half>,
                         cudaFuncAttributeMaxDynamicSharedMemorySize, GEMM_SMEM_BYTES);
    cudaFuncSetAttribute((const void*)gemm_kernel<false, float>,
                         cudaFuncAttributeMaxDynamicSharedMemorySize, GEMM_SMEM_BYTES);

    __half *disp = nullptr, *h = nullptr, *w1h = nullptr, *w2h = nullptr;
    float *y = nullptr;
    cudaGetSymbolAddress((void**)&disp, g_disp);
    cudaGetSymbolAddress((void**)&h, g_h);
    cudaGetSymbolAddress((void**)&y, g_y);
    cudaGetSymbolAddress((void**)&w1h, g_W1h);
    cudaGetSymbolAddress((void**)&w2h, g_W2h);

    init_kernel<<<1, 32>>>();

    {
        dim3 blk(256);
        dim3 t1(F_DIM / 64, C_DIM / 64, E_NUM);
        transpose_h_kernel<<<t1, blk>>>(W1, w1h, C_DIM, F_DIM);
        dim3 t2(C_DIM / 64, F_DIM / 64, E_NUM);
        transpose_h_kernel<<<t2, blk>>>(W2, w2h, F_DIM, C_DIM);
    }

    gate_kernel<<<N_TOK / 8, 256>>>(x, w_gate, b_gate);
    scan_kernel<<<1, 256>>>(out, out_size);
    dispatch_kernel<<<S_SLOTS, 128>>>(x);

    {
        dim3 grid1(F_DIM / GBN, CAP / GBM, E_NUM);
        gemm_kernel<true, __half><<<grid1, 256, GEMM_SMEM_BYTES>>>(
            disp, w1h, b1, h, CAP, F_DIM, C_DIM);

        dim3 grid2(C_DIM / GBN, CAP / GBM, E_NUM);
        gemm_kernel<false, float><<<grid2, 256, GEMM_SMEM_BYTES>>>(
            h, w2h, b2, y, CAP, C_DIM, F_DIM);
    }

    combine_kernel<<<N_TOK, 128>>>(out);
}

// round 8
// speedup vs baseline: 1.0553x; 1.0407x over previous
#include <cuda_runtime.h>
#include <cuda_fp16.h>
#include <cstdint>

// Problem constants
#define N_TOK 8192
#define C_DIM 1024
#define F_DIM 4096
#define E_NUM 8
#define S_SLOTS (N_TOK * 2)
#define CAP 2048

// ---------------- scratch (static device globals) ----------------------------
__device__ __half g_disp[(size_t)E_NUM * CAP * C_DIM];   // 32 MB fp16
__device__ __half g_h[(size_t)E_NUM * CAP * F_DIM];      // 128 MB fp16
__device__ float  g_y[(size_t)E_NUM * CAP * C_DIM];      // 64 MB
__device__ __half g_W1h[(size_t)E_NUM * F_DIM * C_DIM];  // W1^T per expert [F][C] fp16
__device__ __half g_W2h[(size_t)E_NUM * C_DIM * F_DIM];  // W2^T per expert [C][F] fp16
__device__ int    g_eidx[S_SLOTS];
__device__ float  g_wf[S_SLOTS];
__device__ int    g_loc[S_SLOTS];
__device__ int    g_cnt[E_NUM];
__device__ float  g_probs_sum[E_NUM];

// ---------------- helpers ----------------------------------------------------
__device__ __forceinline__ float gelu_tanh(float x) {
    const float k0 = 0.7978845608028654f;
    float x3 = x * x * x;
    float t = tanhf(k0 * (x + 0.044715f * x3));
    return 0.5f * x * (1.0f + t);
}

// fp16 m16n8k16, fp32 accumulate
__device__ __forceinline__ void mma_f16(float* d, const uint32_t* a, const uint32_t* b) {
    asm volatile(
        "mma.sync.aligned.m16n8k16.row.col.f32.f16.f16.f32 "
        "{%0,%1,%2,%3}, {%4,%5,%6,%7}, {%8,%9}, {%0,%1,%2,%3};"
        : "+f"(d[0]), "+f"(d[1]), "+f"(d[2]), "+f"(d[3])
        : "r"(a[0]), "r"(a[1]), "r"(a[2]), "r"(a[3]), "r"(b[0]), "r"(b[1]));
}

__device__ __forceinline__ void cp_async16(uint32_t smem_dst, const void* gmem_src) {
    asm volatile("cp.async.cg.shared.global [%0], [%1], 16;\n" :: "r"(smem_dst), "l"(gmem_src));
}
__device__ __forceinline__ void cp_commit() {
    asm volatile("cp.async.commit_group;\n");
}
template <int N>
__device__ __forceinline__ void cp_wait() {
    asm volatile("cp.async.wait_group %0;\n" :: "n"(N));
}

// ---------------- init -------------------------------------------------------
__global__ void init_kernel() {
    int t = threadIdx.x;
    if (t < E_NUM) g_probs_sum[t] = 0.0f;
}

// ---------------- weight transpose + fp16 convert: [E][K][N] -> [E][N][K] -----
// 64x64 tiles, 256 threads: float4 reads, 16B half stores.
__global__ void transpose_h_kernel(const float* __restrict__ src,
                                   __half* __restrict__ dst, int K, int N) {
    __shared__ float t[64][65];
    int e = blockIdx.z;
    const float* s = src + (size_t)e * K * N;
    __half* d = dst + (size_t)e * N * K;
    int n0 = blockIdx.x * 64, k0 = blockIdx.y * 64;
    int tid = threadIdx.x;

    {
        int r = tid >> 4, c4 = tid & 15;
#pragma unroll
        for (int p = 0; p < 4; p++) {
            float4 v = *(const float4*)(s + (size_t)(k0 + r + p * 16) * N + n0 + c4 * 4);
            t[r + p * 16][c4 * 4 + 0] = v.x;
            t[r + p * 16][c4 * 4 + 1] = v.y;
            t[r + p * 16][c4 * 4 + 2] = v.z;
            t[r + p * 16][c4 * 4 + 3] = v.w;
        }
    }
    __syncthreads();

    {
        int n = tid >> 3, c8 = tid & 7;
#pragma unroll
        for (int p = 0; p < 2; p++) {
            int nn = n + p * 32;
            __half2 h[4];
#pragma unroll
            for (int j = 0; j < 4; j++)
                h[j] = __floats2half2_rn(t[c8 * 8 + 2 * j][nn], t[c8 * 8 + 2 * j + 1][nn]);
            *(uint4*)(d + (size_t)(n0 + nn) * K + k0 + c8 * 8) = *(uint4*)h;
        }
    }
}

// ---------------- gating (scalar x loads, Round-5 proven 35us version) --------
__global__ void gate_kernel(const float* __restrict__ x,
                            const float* __restrict__ w_gate,
                            const float* __restrict__ b_gate) {
    __shared__ float sprob[E_NUM];
    int tid = threadIdx.x;
    if (tid < E_NUM) sprob[tid] = 0.0f;
    __syncthreads();

    int warp = tid >> 5, lane = tid & 31;
    int n = blockIdx.x * 8 + warp;
    const float* xr = x + (size_t)n * C_DIM;

    float acc[E_NUM];
#pragma unroll
    for (int e = 0; e < E_NUM; e++) acc[e] = 0.0f;

    for (int c = lane; c < C_DIM; c += 32) {
        float xv = xr[c];
        const float4* w4 = (const float4*)(w_gate + (size_t)c * E_NUM);
        float4 wa = w4[0], wb = w4[1];
        acc[0] += xv * wa.x; acc[1] += xv * wa.y;
        acc[2] += xv * wa.z; acc[3] += xv * wa.w;
        acc[4] += xv * wb.x; acc[5] += xv * wb.y;
        acc[6] += xv * wb.z; acc[7] += xv * wb.w;
    }
#pragma unroll
    for (int e = 0; e < E_NUM; e++)
#pragma unroll
        for (int o = 16; o > 0; o >>= 1)
            acc[e] += __shfl_down_sync(0xffffffffu, acc[e], o);

    if (lane == 0) {
        float p[E_NUM];
        float mx = -1e30f;
#pragma unroll
        for (int e = 0; e < E_NUM; e++) { p[e] = acc[e] + b_gate[e]; mx = fmaxf(mx, p[e]); }
        float s = 0.0f;
#pragma unroll
        for (int e = 0; e < E_NUM; e++) { p[e] = expf(p[e] - mx); s += p[e]; }
        float inv = 1.0f / s;
#pragma unroll
        for (int e = 0; e < E_NUM; e++) p[e] *= inv;

        int i0 = 0;
#pragma unroll
        for (int e = 1; e < E_NUM; e++) if (p[e] > p[i0]) i0 = e;
        int i1 = (i0 == 0) ? 1 : 0;
#pragma unroll
        for (int e = 0; e < E_NUM; e++) if (e != i0 && p[e] > p[i1]) i1 = e;

        float w0 = p[i0], w1 = p[i1];
        float ws = w0 + w1 + 1e-9f;
        g_eidx[2 * n]     = i0;
        g_eidx[2 * n + 1] = i1;
        g_wf[2 * n]       = w0 / ws;
        g_wf[2 * n + 1]   = w1 / ws;
#pragma unroll
        for (int e = 0; e < E_NUM; e++) atomicAdd(&sprob[e], p[e]);
    }
    __syncthreads();
    if (tid < E_NUM) atomicAdd(&g_probs_sum[tid], sprob[tid]);
}

// ---------------- FCFS capacity scan + aux loss --------------------------------
__global__ void scan_kernel(float* __restrict__ d_out, int out_size) {
    const int PER = 64;
    int t = threadIdx.x;
    int base = t * PER;

    int cnt[E_NUM];
#pragma unroll
    for (int e = 0; e < E_NUM; e++) cnt[e] = 0;
    for (int i = 0; i < PER; i++) cnt[g_eidx[base + i]]++;

    unsigned long long lo = 0, hi = 0;
#pragma unroll
    for (int e = 0; e < 4; e++) {
        lo |= (unsigned long long)cnt[e] << (16 * e);
        hi |= (unsigned long long)cnt[e + 4] << (16 * e);
    }

    __shared__ unsigned long long s0[256], s1[256];
    s0[t] = lo; s1[t] = hi;
    __syncthreads();
    for (int off = 1; off < 256; off <<= 1) {
        unsigned long long v0 = 0, v1 = 0;
        if (t >= off) { v0 = s0[t - off]; v1 = s1[t - off]; }
        __syncthreads();
        s0[t] += v0; s1[t] += v1;
        __syncthreads();
    }
    unsigned long long p0 = (t > 0) ? s0[t - 1] : 0ULL;
    unsigned long long p1 = (t > 0) ? s1[t - 1] : 0ULL;

    int exc[E_NUM];
#pragma unroll
    for (int e = 0; e < 4; e++) {
        exc[e]     = (int)((p0 >> (16 * e)) & 0xffffULL);
        exc[e + 4] = (int)((p1 >> (16 * e)) & 0xffffULL);
    }
    for (int i = 0; i < PER; i++) {
        int s = base + i;
        int e = g_eidx[s];
        int pos = exc[e]++;
        g_loc[s] = (pos < CAP) ? (e * CAP + pos) : -1;
    }

    if (t == 0) {
        unsigned long long t0 = s0[255], t1 = s1[255];
        float sumload = 0.0f, load[E_NUM];
#pragma unroll
        for (int e = 0; e < 4; e++) {
            int c0 = (int)((t0 >> (16 * e)) & 0xffffULL);
            int c1 = (int)((t1 >> (16 * e)) & 0xffffULL);
            g_cnt[e]     = min(c0, CAP);
            g_cnt[e + 4] = min(c1, CAP);
            load[e]     = (float)min(c0, CAP);
            load[e + 4] = (float)min(c1, CAP);
        }
#pragma unroll
        for (int e = 0; e < E_NUM; e++) sumload += load[e];
        float fe[E_NUM], sfe = 0.0f;
#pragma unroll
        for (int e = 0; e < E_NUM; e++) { fe[e] = g_probs_sum[e] / (float)N_TOK; sfe += fe[e]; }
        float aux = 0.0f;
#pragma unroll
        for (int e = 0; e < E_NUM; e++) {
            float fn = fe[e] / (sfe + 1e-9f);
            float fa = load[e] / (sumload + 1e-9f);
            float d = fn - fa;
            aux += d * d;
        }
        aux = 0.01f * aux / (float)E_NUM;
        if (out_size > N_TOK * C_DIM)
            d_out[(size_t)N_TOK * C_DIM] = aux;
    }
}

// ---------------- dispatch gather (fp16 convert at write) ----------------------
__global__ void dispatch_kernel(const float* __restrict__ x) {
    int s = blockIdx.x;
    int loc = g_loc[s];
    if (loc < 0) return;
    const float4* src = (const float4*)(x + ((size_t)(s >> 1)) * C_DIM);
    __half* dst = g_disp + (size_t)loc * C_DIM;
    int t = threadIdx.x;  // 128
    float4 v0 = src[2 * t];
    float4 v1 = src[2 * t + 1];
    __half2 h[4];
    h[0] = __floats2half2_rn(v0.x, v0.y);
    h[1] = __floats2half2_rn(v0.z, v0.w);
    h[2] = __floats2half2_rn(v1.x, v1.y);
    h[3] = __floats2half2_rn(v1.z, v1.w);
    *(uint4*)(dst + 8 * t) = *(uint4*)h;
}

// ---------------- grouped GEMM: fp16 mma.sync m16n8k16, 5-stage cp.async ------
#define GBM 128
#define GBN 128
#define GBK 32
#define GST 5
#define LDH 40
#define ASZH (GBM * LDH)
#define BSZH (GBN * LDH)
#define STG_BYTES ((ASZH + BSZH) * 2)              // 20480
#define GEMM_SMEM_BYTES (GST * STG_BYTES)          // 102400

template <bool GELU, typename OT>
__global__ __launch_bounds__(256, 2)
void gemm_kernel(const __half* __restrict__ A, const __half* __restrict__ Bt,
                 const float* __restrict__ bias, OT* __restrict__ Out,
                 int M, int N, int Kd) {
    int e = blockIdx.z;
    int bm = blockIdx.y, bn = blockIdx.x;
    if (bm * GBM >= g_cnt[e]) return;   // rows never read downstream

    extern __shared__ __half smem[];
    __half* Asm = smem;
    __half* Bsm = smem + GST * ASZH;

    const __half* Ae = A + (size_t)e * M * Kd;
    const __half* Be = Bt + (size_t)e * N * Kd;
    OT* Oe = Out + (size_t)e * M * N;

    int tid = threadIdx.x;
    int warp = tid >> 5, lane = tid & 31;
    int g = lane >> 2, tig = lane & 3;
    int wm = warp >> 2;
    int wn = warp & 3;

    uint32_t sA = (uint32_t)__cvta_generic_to_shared(Asm);
    uint32_t sB = (uint32_t)__cvta_generic_to_shared(Bsm);

    const int nK = Kd / GBK;

    auto issue = [&](int kt, int st) {
        uint32_t aBase = sA + (uint32_t)(st * ASZH) * 2;
        uint32_t bBase = sB + (uint32_t)(st * BSZH) * 2;
#pragma unroll
        for (int i = 0; i < 2; i++) {
            int ch = tid + 256 * i;
            int r = ch >> 2, c = (ch & 3) * 8;
            cp_async16(aBase + (uint32_t)(r * LDH + c) * 2,
                       Ae + (size_t)(bm * GBM + r) * Kd + kt * GBK + c);
        }
#pragma unroll
        for (int i = 0; i < 2; i++) {
            int ch = tid + 256 * i;
            int r = ch >> 2, c = (ch & 3) * 8;
            cp_async16(bBase + (uint32_t)(r * LDH + c) * 2,
                       Be + (size_t)(bn * GBN + r) * Kd + kt * GBK + c);
        }
        cp_commit();
    };

    // prologue: fill stages 0..GST-2
#pragma unroll
    for (int s = 0; s < GST - 1; s++) issue(s, s);

    float acc[4][4][4];
#pragma unroll
    for (int i = 0; i < 4; i++)
#pragma unroll
        for (int j = 0; j < 4; j++)
#pragma unroll
            for (int k = 0; k < 4; k++) acc[i][j][k] = 0.0f;

    for (int kt = 0; kt < nK; kt++) {
        int rem = nK - 1 - kt;   // groups allowed to stay pending
        if (rem >= GST - 2)      cp_wait<GST - 2>();
        else if (rem == 2)       cp_wait<2>();
        else if (rem == 1)       cp_wait<1>();
        else                     cp_wait<0>();
        // Single barrier per iteration: also orders "all warps done reading
        // stage (kt-1)%GST during iter kt-1" before the issue below overwrites it.
        __syncthreads();

        int nt = kt + GST - 1;
        if (nt < nK) issue(nt, nt % GST);

        const __half* as = Asm + (kt % GST) * ASZH;
        const __half* bs = Bsm + (kt % GST) * BSZH;

#pragma unroll
        for (int kk = 0; kk < 2; kk++) {
            int kb = kk * 16;
            uint32_t af[4][4];
#pragma unroll
            for (int mt = 0; mt < 4; mt++) {
                int r0 = wm * 64 + mt * 16 + g;
                af[mt][0] = *(const uint32_t*)&as[r0 * LDH + kb + 2 * tig];
                af[mt][1] = *(const uint32_t*)&as[(r0 + 8) * LDH + kb + 2 * tig];
                af[mt][2] = *(const uint32_t*)&as[r0 * LDH + kb + 8 + 2 * tig];
                af[mt][3] = *(const uint32_t*)&as[(r0 + 8) * LDH + kb + 8 + 2 * tig];
            }
            uint32_t bf[4][2];
#pragma unroll
            for (int nt2 = 0; nt2 < 4; nt2++) {
                int c0 = wn * 32 + nt2 * 8 + g;
                bf[nt2][0] = *(const uint32_t*)&bs[c0 * LDH + kb + 2 * tig];
                bf[nt2][1] = *(const uint32_t*)&bs[c0 * LDH + kb + 8 + 2 * tig];
            }
#pragma unroll
            for (int mt = 0; mt < 4; mt++)
#pragma unroll
                for (int nt2 = 0; nt2 < 4; nt2++)
                    mma_f16(acc[mt][nt2], af[mt], bf[nt2]);
        }
    }

    // epilogue
#pragma unroll
    for (int mt = 0; mt < 4; mt++) {
        int r0 = bm * GBM + wm * 64 + mt * 16 + g;
#pragma unroll
        for (int nt2 = 0; nt2 < 4; nt2++) {
            int c0 = bn * GBN + wn * 32 + nt2 * 8 + 2 * tig;
            float bv0 = bias[(size_t)e * N + c0];
            float bv1 = bias[(size_t)e * N + c0 + 1];
            float v00 = acc[mt][nt2][0] + bv0;
            float v01 = acc[mt][nt2][1] + bv1;
            float v10 = acc[mt][nt2][2] + bv0;
            float v11 = acc[mt][nt2][3] + bv1;
            if (GELU) {
                v00 = gelu_tanh(v00); v01 = gelu_tanh(v01);
                v10 = gelu_tanh(v10); v11 = gelu_tanh(v11);
            }
            if constexpr (sizeof(OT) == 2) {
                *(__half2*)((__half*)Oe + (size_t)r0 * N + c0) = __floats2half2_rn(v00, v01);
                *(__half2*)((__half*)Oe + (size_t)(r0 + 8) * N + c0) = __floats2half2_rn(v10, v11);
            } else {
                *(float2*)((float*)Oe + (size_t)r0 * N + c0) = make_float2(v00, v01);
                *(float2*)((float*)Oe + (size_t)(r0 + 8) * N + c0) = make_float2(v10, v11);
            }
        }
    }
}

// ---------------- combine gather ---------------------------------------------
__global__ void combine_kernel(float* __restrict__ out) {
    int n = blockIdx.x;
    int l0 = g_loc[2 * n], l1 = g_loc[2 * n + 1];
    float w0 = (l0 >= 0) ? g_wf[2 * n] : 0.0f;
    float w1 = (l1 >= 0) ? g_wf[2 * n + 1] : 0.0f;
    const float4* y0 = (const float4*)(g_y + (size_t)max(l0, 0) * C_DIM);
    const float4* y1 = (const float4*)(g_y + (size_t)max(l1, 0) * C_DIM);
    float4* dst = (float4*)(out + (size_t)n * C_DIM);
    int t = threadIdx.x;  // 128
#pragma unroll
    for (int j = 0; j < 2; j++) {
        int idx = t + j * 128;
        float4 a = (l0 >= 0) ? y0[idx] : make_float4(0, 0, 0, 0);
        float4 b = (l1 >= 0) ? y1[idx] : make_float4(0, 0, 0, 0);
        float4 r;
        r.x = w0 * a.x + w1 * b.x;
        r.y = w0 * a.y + w1 * b.y;
        r.z = w0 * a.z + w1 * b.z;
        r.w = w0 * a.w + w1 * b.w;
        dst[idx] = r;
    }
}

// ---------------- launcher ----------------------------------------------------
extern "C" void kernel_launch(void* const* d_in, const int* in_sizes, int n_in,
                              void* d_out, int out_size) {
    const float* x      = (const float*)d_in[0];
    const float* w_gate = (const float*)d_in[1];
    const float* b_gate = (const float*)d_in[2];
    const float* W1     = (const float*)d_in[3];
    const float* b1     = (const float*)d_in[4];
    const float* W2     = (const float*)d_in[5];
    const float* b2     = (const float*)d_in[6];
    float* out = (float*)d_out;

    cudaFuncSetAttribute((const void*)gemm_kernel<true, __half>,
                         cudaFuncAttributeMaxDynamicSharedMemorySize, GEMM_SMEM_BYTES);
    cudaFuncSetAttribute((const void*)gemm_kernel<false, float>,
                         cudaFuncAttributeMaxDynamicSharedMemorySize, GEMM_SMEM_BYTES);

    __half *disp = nullptr, *h = nullptr, *w1h = nullptr, *w2h = nullptr;
    float *y = nullptr;
    cudaGetSymbolAddress((void**)&disp, g_disp);
    cudaGetSymbolAddress((void**)&h, g_h);
    cudaGetSymbolAddress((void**)&y, g_y);
    cudaGetSymbolAddress((void**)&w1h, g_W1h);
    cudaGetSymbolAddress((void**)&w2h, g_W2h);

    init_kernel<<<1, 32>>>();

    {
        dim3 blk(256);
        dim3 t1(F_DIM / 64, C_DIM / 64, E_NUM);
        transpose_h_kernel<<<t1, blk>>>(W1, w1h, C_DIM, F_DIM);
        dim3 t2(C_DIM / 64, F_DIM / 64, E_NUM);
        transpose_h_kernel<<<t2, blk>>>(W2, w2h, F_DIM, C_DIM);
    }

    gate_kernel<<<N_TOK / 8, 256>>>(x, w_gate, b_gate);
    scan_kernel<<<1, 256>>>(out, out_size);
    dispatch_kernel<<<S_SLOTS, 128>>>(x);

    {
        dim3 grid1(F_DIM / GBN, CAP / GBM, E_NUM);
        gemm_kernel<true, __half><<<grid1, 256, GEMM_SMEM_BYTES>>>(
            disp, w1h, b1, h, CAP, F_DIM, C_DIM);

        dim3 grid2(C_DIM / GBN, CAP / GBM, E_NUM);
        gemm_kernel<false, float><<<grid2, 256, GEMM_SMEM_BYTES>>>(
            h, w2h, b2, y, CAP, C_DIM, F_DIM);
    }

    combine_kernel<<<N_TOK, 128>>>(out);
}